// round 14
// baseline (speedup 1.0000x reference)
#include <cuda_runtime.h>

#define NWIRES  12
#define DIM     4096
#define NLAYERS 4
#define NT      256

// dynamic smem layout (bytes)
#define OFF_BUF1 32768
#define OFF_UG   65536
#define OFF_SC   (65536 + 768)
#define OFF_RED  (65536 + 768 + 1184)
#define SMEM_TOTAL (65536 + 768 + 1184 + 256)

__device__ __forceinline__ float2 cmul(float2 a, float2 b) {
    return make_float2(fmaf(a.x, b.x, -(a.y * b.y)),
                       fmaf(a.x, b.y,   a.y * b.x));
}

// GF(2)-linear nibble helpers
__device__ __forceinline__ int tau(int n)  { return n ^ ((n << 1) & 14); }
__device__ __forceinline__ int pj(int j)   { return j ^ tau((j >> 4) & 15); }   // layout A
__device__ __forceinline__ int mrot(int x) { return ((x & 7) << 1) | ((x >> 3) & 1); }
__device__ __forceinline__ int hperm(int j) {                                    // CNOT-chain g^{-1}
    j ^= j >> 1; j ^= j >> 2; j ^= j >> 4; j ^= j >> 8;
    return j;
}

// SU(2) butterfly, staged by shared multiplicand.
// g = (u00r, u00i, u01r, u01i); u10 = -conj(u01), u11 = conj(u00).
__device__ __forceinline__ void bfly(float4 g, float& r0, float& i0, float& r1, float& i1) {
    const float a = r0, b = i0, c = r1, d = i1;
    float n0 =  g.x * a;
    float n1 =  g.y * a;
    float n2 = -g.z * a;
    float n3 =  g.w * a;
    n0 = fmaf(-g.y, b, n0);
    n1 = fmaf( g.x, b, n1);
    n2 = fmaf(-g.w, b, n2);
    n3 = fmaf(-g.z, b, n3);
    n0 = fmaf( g.z, c, n0);
    n1 = fmaf( g.w, c, n1);
    n2 = fmaf( g.x, c, n2);
    n3 = fmaf(-g.y, c, n3);
    n0 = fmaf(-g.w, d, n0);
    n1 = fmaf( g.z, d, n1);
    n2 = fmaf( g.y, d, n2);
    n3 = fmaf( g.x, d, n3);
    r0 = n0; i0 = n1; r1 = n2; i1 = n3;
}

// ---- round 0: vector gather from layout A (validated in R13) ----
// slot 2l+j holds logical n0 = 2l + (j ^ (t&1)); stage 0 role-swaps for odd t.
template <int L>
__device__ __forceinline__ void gather_apply0(const float2* __restrict__ st,
                                              const float4* __restrict__ Ug,
                                              int t, float* re, float* im) {
    const int s = ((t >> 1) & 7) ^ (t & 7);
    const float4* blk = ((const float4*)st) + (t << 3);
    #pragma unroll
    for (int l = 0; l < 8; ++l) {
        const float4 q = blk[l ^ s];
        re[2 * l] = q.x;  im[2 * l] = q.y;
        re[2 * l + 1] = q.z;  im[2 * l + 1] = q.w;
    }
    {
        float4 g = Ug[L * NWIRES + 11];
        if (t & 1) { g.y = -g.y; g.z = -g.z; }
        #pragma unroll
        for (int p = 0; p < 8; ++p)
            bfly(g, re[2 * p], im[2 * p], re[2 * p + 1], im[2 * p + 1]);
    }
    #pragma unroll
    for (int lb = 1; lb < 4; ++lb) {
        const float4 g = Ug[L * NWIRES + (11 - lb)];
        const int str = 1 << lb;
        #pragma unroll
        for (int p = 0; p < 8; ++p) {
            const int i0 = ((p & ~(str - 1)) << 1) | (p & (str - 1));
            const int i1 = i0 | str;
            bfly(g, re[i0], im[i0], re[i1], im[i1]);
        }
    }
}

// round-0 scatter into layout B: phys = (n2<<8)|(n0<<4)|(n1 ^ mrot(n0)).
// slot w holds logical n0 = w ^ (t&1); F(v)=(v<<4)|mrot(v), F(1)=18.
__device__ __forceinline__ void scatter0B(float2* __restrict__ st, int t,
                                          const float* re, const float* im) {
    const int base = (((t >> 4) << 8) | (t & 15)) ^ ((t & 1) ? 18 : 0);
    #pragma unroll
    for (int w = 0; w < 16; ++w)
        st[base ^ ((w << 4) | mrot(w))] = make_float2(re[w], im[w]);
}

// ---- rounds 1,2: vector gather from layout B/C ----
// reader base = ((t>>4)<<8)|((t&15)<<4); granule k^(t&7) holds logical pair k;
// within-pair swap iff t bit 3 -> stage-0 role swap. Gates on bits 4R..4R+3.
template <int L, int R>
__device__ __forceinline__ void gather_applyBC(const float2* __restrict__ st,
                                               const float4* __restrict__ Ug,
                                               int t, float* re, float* im) {
    const int tb3 = (t >> 3) & 1;
    const float4* blk = ((const float4*)st) + (((t >> 4) << 7) | ((t & 15) << 3));
    #pragma unroll
    for (int k = 0; k < 8; ++k) {
        const float4 q = blk[k ^ (t & 7)];
        re[2 * k] = q.x;  im[2 * k] = q.y;
        re[2 * k + 1] = q.z;  im[2 * k + 1] = q.w;
    }
    {
        float4 g = Ug[L * NWIRES + (11 - 4 * R)];
        if (tb3) { g.y = -g.y; g.z = -g.z; }
        #pragma unroll
        for (int p = 0; p < 8; ++p)
            bfly(g, re[2 * p], im[2 * p], re[2 * p + 1], im[2 * p + 1]);
    }
    #pragma unroll
    for (int lb = 1; lb < 4; ++lb) {
        const float4 g = Ug[L * NWIRES + (11 - (4 * R + lb))];
        const int str = 1 << lb;
        #pragma unroll
        for (int p = 0; p < 8; ++p) {
            const int i0 = ((p & ~(str - 1)) << 1) | (p & (str - 1));
            const int i1 = i0 | str;
            bfly(g, re[i0], im[i0], re[i1], im[i1]);
        }
    }
}

// round-1 scatter into layout C: phys = (n1<<8)|(n0<<4)|(n2 ^ mrot(n0)).
// writer: n2 = t>>4, n0 = t&15, n1 = w ^ tb3.
__device__ __forceinline__ void scatter1C(float2* __restrict__ st, int t,
                                          const float* re, const float* im) {
    const int tb3 = (t >> 3) & 1;
    const int base = (((t & 15) << 4) | ((t >> 4) ^ mrot(t & 15))) ^ (tb3 << 8);
    #pragma unroll
    for (int w = 0; w < 16; ++w)
        st[base ^ (w << 8)] = make_float2(re[w], im[w]);
}

// round-2 h-scatter into layout A of the other buffer.
// slot w holds logical n2 = w ^ tb3; pj∘hperm is GF(2)-linear.
__device__ __forceinline__ void hscatter(float2* __restrict__ st, int t,
                                         const float* re, const float* im) {
    const int tb3 = (t >> 3) & 1;
    const int hb2 = pj(hperm(t)) ^ (tb3 ? pj(hperm(256)) : 0);
    #pragma unroll
    for (int w = 0; w < 16; ++w)
        st[hb2 ^ pj(hperm(w << 8))] = make_float2(re[w], im[w]);
}

__global__ __launch_bounds__(NT, 3)
void qnn_kernel(const float* __restrict__ x, const float* __restrict__ w,
                float* __restrict__ out)
{
    extern __shared__ char smem[];
    float2* buf0 = (float2*)smem;
    float2* buf1 = (float2*)(smem + OFF_BUF1);
    float4* Ug   = (float4*)(smem + OFF_UG);
    float2* sc   = (float2*)(smem + OFF_SC);
    float*  red  = (float*)(smem + OFF_RED);

    const int b = blockIdx.x;
    const int t = threadIdx.x;

    // ---- parallel sincos: one per thread ----
    if (t < 144) {
        float s, c;
        sincosf(0.5f * w[t], &s, &c);
        sc[t] = make_float2(c, s);
    } else if (t < 146) {
        float s, c;
        sincosf(0.5f * x[b * 2 + (t - 144)], &s, &c);
        sc[t] = make_float2(c, s);
    }
    __syncthreads();

    // ---- assemble fused SU(2) gates U = RZ RY RX @ Enc (48 threads) ----
    if (t < NLAYERS * NWIRES) {
        const int wi = t % NWIRES;
        const float2 A  = sc[t * 3 + 0];
        const float2 Bc = sc[t * 3 + 1];
        const float2 G  = sc[t * 3 + 2];
        float2 m00 = make_float2( Bc.x * A.x,  Bc.y * A.y);
        float2 m01 = make_float2(-Bc.y * A.x, -Bc.x * A.y);
        const float2 e0 = make_float2(G.x, -G.y);
        m00 = cmul(e0, m00); m01 = cmul(e0, m01);
        const float2 E = sc[144 + (wi & 1)];
        float2 u00, u01;
        if (wi & 1) { // RY encoding
            u00 = make_float2(fmaf(m00.x, E.x,  m01.x * E.y),
                              fmaf(m00.y, E.x,  m01.y * E.y));
            u01 = make_float2(fmaf(m00.x, -E.y, m01.x * E.x),
                              fmaf(m00.y, -E.y, m01.y * E.x));
        } else {      // RX encoding
            u00 = make_float2(fmaf(m00.x, E.x,  m01.y * E.y),
                              fmaf(m00.y, E.x, -(m01.x * E.y)));
            u01 = make_float2(fmaf(m01.x, E.x,  m00.y * E.y),
                              fmaf(m01.y, E.x, -(m00.x * E.y)));
        }
        Ug[t] = make_float4(u00.x, u00.y, u01.x, u01.y);
    }
    __syncthreads();

    // ---- layer 0 on |0..0>: product state via tensor tree, h-stored (layout A, buf0) ----
    {
        float2 pt = make_float2(1.f, 0.f);
        #pragma unroll
        for (int bit = 0; bit < 8; ++bit) {
            const int row = (t >> bit) & 1;
            const float4 g = Ug[11 - bit];
            const float cr = row ? -g.z : g.x;
            const float ci = row ?  g.w : g.y;
            pt = cmul(make_float2(cr, ci), pt);
        }
        float2 e3[2], e2[2], e1[2], e0c[2];
        {
            const float4 g3 = Ug[3], g2 = Ug[2], g1 = Ug[1], g0 = Ug[0];
            e3[0] = make_float2(g3.x, g3.y);  e3[1] = make_float2(-g3.z, g3.w);
            e2[0] = make_float2(g2.x, g2.y);  e2[1] = make_float2(-g2.z, g2.w);
            e1[0] = make_float2(g1.x, g1.y);  e1[1] = make_float2(-g1.z, g1.w);
            e0c[0] = make_float2(g0.x, g0.y); e0c[1] = make_float2(-g0.z, g0.w);
        }
        float2 PA[4], PB[4];
        #pragma unroll
        for (int a = 0; a < 4; ++a)
            PA[a] = cmul(cmul(e3[a & 1], e2[(a >> 1) & 1]), pt);
        #pragma unroll
        for (int bb = 0; bb < 4; ++bb)
            PB[bb] = cmul(e1[bb & 1], e0c[(bb >> 1) & 1]);
        const int hb = pj(hperm(t));
        #pragma unroll
        for (int v = 0; v < 16; ++v)
            buf0[hb ^ pj(hperm(v << 8))] = cmul(PA[v & 3], PB[v >> 2]);
    }
    __syncthreads();

    float re[16], im[16];

    // ---- layers 1..3: ping-pong; every gather is 8x LDS.128 ----
    #define DO_LAYER(L, I, O)                                                  \
        gather_apply0<L>(I, Ug, t, re, im);                                    \
        scatter0B(O, t, re, im);                                               \
        __syncthreads();           /* B visible; I(A) fully read */            \
        gather_applyBC<L, 1>(O, Ug, t, re, im);                                \
        scatter1C(I, t, re, im);                                               \
        __syncthreads();           /* C visible; O(B) fully read */            \
        gather_applyBC<L, 2>(I, Ug, t, re, im);

    DO_LAYER(1, buf0, buf1)
    hscatter(buf1, t, re, im);     // -> layout A in buf1 (buf1(B) fully read)
    __syncthreads();

    DO_LAYER(2, buf1, buf0)
    hscatter(buf0, t, re, im);     // -> layout A in buf0
    __syncthreads();

    DO_LAYER(3, buf0, buf1)        // last gather feeds measurement directly

    // ---- measurement straight from registers ----
    // slot w holds logical v = w ^ tb3 (bit 0 only) -> flip dpar for tb3
    const int tb3m = (t >> 3) & 1;
    float acc0 = 0.f, acc1 = 0.f, acc2 = 0.f, dpar = 0.f;
    #pragma unroll
    for (int v = 0; v < 16; ++v) {
        const float p = fmaf(re[v], re[v], im[v] * im[v]);
        const int v3 = (v >> 3) & 1, v2 = (v >> 2) & 1, v1 = (v >> 1) & 1, v0 = v & 1;
        acc0 += v3 ? -p : p;
        acc1 += (v3 ^ v2) ? -p : p;
        acc2 += (v3 ^ v2 ^ v1) ? -p : p;
        dpar += (v3 ^ v2 ^ v1 ^ v0) ? -p : p;
    }
    if (tb3m) dpar = -dpar;
    const int t4 = (t >> 4) & 1;
    float d4 = t4 ? -dpar : dpar;

    const unsigned FULL = 0xffffffffu;
    float vals[5] = {acc0, acc1, acc2, dpar, d4};
    #pragma unroll
    for (int i = 0; i < 5; ++i) {
        float v = vals[i];
        #pragma unroll
        for (int o = 16; o > 0; o >>= 1) v += __shfl_xor_sync(FULL, v, o);
        vals[i] = v;
    }
    if ((t & 31) == 0) {
        const int wp = t >> 5;
        const int t7 = (t >> 7) & 1, t6 = (t >> 6) & 1, t5 = (t >> 5) & 1;
        const float D = vals[3], D4 = vals[4];
        red[wp * 8 + 0] = vals[0];
        red[wp * 8 + 1] = vals[1];
        red[wp * 8 + 2] = vals[2];
        red[wp * 8 + 3] = D;
        red[wp * 8 + 4] = t7 ? -D : D;
        red[wp * 8 + 5] = (t7 ^ t6) ? -D : D;
        red[wp * 8 + 6] = (t7 ^ t6 ^ t5) ? -D : D;
        red[wp * 8 + 7] = (t7 ^ t6 ^ t5) ? -D4 : D4;
    }
    __syncthreads();
    if (t < 8) {
        float s = 0.f;
        #pragma unroll
        for (int wp2 = 0; wp2 < 8; ++wp2) s += red[wp2 * 8 + t];
        out[b * 8 + t] = s * 3.14159265358979f;
    }
}

extern "C" void kernel_launch(void* const* d_in, const int* in_sizes, int n_in,
                              void* d_out, int out_size) {
    const float* x = (const float*)d_in[0];   // [B, 2]
    const float* w = (const float*)d_in[1];   // [4, 12, 3]
    float* out = (float*)d_out;               // [B, 8]
    const int B = in_sizes[0] / 2;
    cudaFuncSetAttribute(qnn_kernel, cudaFuncAttributeMaxDynamicSharedMemorySize, SMEM_TOTAL);
    qnn_kernel<<<B, NT, SMEM_TOTAL>>>(x, w, out);
}

// round 15
// speedup vs baseline: 1.0578x; 1.0578x over previous
#include <cuda_runtime.h>

#define NWIRES  12
#define DIM     4096
#define NLAYERS 4
#define NT      256

// dynamic smem layout (bytes)
#define OFF_BUF1 32768
#define OFF_UG   65536
#define OFF_SC   (65536 + 768)
#define OFF_RED  (65536 + 768 + 1184)
#define SMEM_TOTAL (65536 + 768 + 1184 + 256)

__device__ __forceinline__ float2 cmul(float2 a, float2 b) {
    return make_float2(fmaf(a.x, b.x, -(a.y * b.y)),
                       fmaf(a.x, b.y,   a.y * b.x));
}

// GF(2)-linear nibble mask: tau(n) = n ^ ((n<<1)&14)
__device__ __forceinline__ int tau(int n) { return n ^ ((n << 1) & 14); }
// global logical->physical float2 map (layout A): P(j) = j ^ tau((j>>4)&15)
__device__ __forceinline__ int pj(int j) { return j ^ tau((j >> 4) & 15); }
// h = g^{-1} (prefix-XOR) of the CNOT-chain permutation
__device__ __forceinline__ int hperm(int j) {
    j ^= j >> 1; j ^= j >> 2; j ^= j >> 4; j ^= j >> 8;
    return j;
}

// SU(2) butterfly, staged by shared multiplicand.
// g = (u00r, u00i, u01r, u01i); u10 = -conj(u01), u11 = conj(u00).
__device__ __forceinline__ void bfly(float4 g, float& r0, float& i0, float& r1, float& i1) {
    const float a = r0, b = i0, c = r1, d = i1;
    float n0 =  g.x * a;
    float n1 =  g.y * a;
    float n2 = -g.z * a;
    float n3 =  g.w * a;
    n0 = fmaf(-g.y, b, n0);
    n1 = fmaf( g.x, b, n1);
    n2 = fmaf(-g.w, b, n2);
    n3 = fmaf(-g.z, b, n3);
    n0 = fmaf( g.z, c, n0);
    n1 = fmaf( g.w, c, n1);
    n2 = fmaf( g.x, c, n2);
    n3 = fmaf(-g.y, c, n3);
    n0 = fmaf(-g.w, d, n0);
    n1 = fmaf( g.z, d, n1);
    n2 = fmaf( g.y, d, n2);
    n3 = fmaf( g.x, d, n3);
    r0 = n0; i0 = n1; r1 = n2; i1 = n3;
}

// ---- round 0: vector gather (8x LDS.128, bank-validated in R13) ----
// slot 2l+j holds logical n0 = 2l + (j ^ (t&1)); stage 0 role-swaps for odd t.
template <int L>
__device__ __forceinline__ void gather_apply0(const float2* __restrict__ st,
                                              const float4* __restrict__ Ug,
                                              int t, float* re, float* im) {
    const int s = ((t >> 1) & 7) ^ (t & 7);
    const float4* blk = ((const float4*)st) + (t << 3);
    #pragma unroll
    for (int l = 0; l < 8; ++l) {
        const float4 q = blk[l ^ s];
        re[2 * l] = q.x;  im[2 * l] = q.y;
        re[2 * l + 1] = q.z;  im[2 * l + 1] = q.w;
    }
    {
        float4 g = Ug[L * NWIRES + 11];
        if (t & 1) { g.y = -g.y; g.z = -g.z; }
        #pragma unroll
        for (int p = 0; p < 8; ++p)
            bfly(g, re[2 * p], im[2 * p], re[2 * p + 1], im[2 * p + 1]);
    }
    #pragma unroll
    for (int lb = 1; lb < 4; ++lb) {
        const float4 g = Ug[L * NWIRES + (11 - lb)];
        const int str = 1 << lb;
        #pragma unroll
        for (int p = 0; p < 8; ++p) {
            const int i0 = ((p & ~(str - 1)) << 1) | (p & (str - 1));
            const int i1 = i0 | str;
            bfly(g, re[i0], im[i0], re[i1], im[i1]);
        }
    }
}
__device__ __forceinline__ void scatter0(float2* __restrict__ st, int t,
                                         const float* re, const float* im) {
    const int s = ((t >> 1) & 7) ^ (t & 7);
    float4* blk = ((float4*)st) + (t << 3);
    #pragma unroll
    for (int l = 0; l < 8; ++l)
        blk[l ^ s] = make_float4(re[2 * l], im[2 * l], re[2 * l + 1], im[2 * l + 1]);
}

// ---- rounds 1,2: scalar, XOR-decomposed addressing under pj ----
template <int R> __device__ __forceinline__ int abase(int t) {
    if (R == 1) return ((t & 0xF0) << 4) | (t & 15);     // pj(T1)=T1 (high nibble 0)
    return t ^ tau((t >> 4) & 15);                        // R==2: pj(t)
}
template <int R> __device__ __forceinline__ int aoff(int v) {
    if (R == 1) return (v << 4) ^ tau(v);                 // pj(v<<4)
    return v << 8;                                        // pj(v<<8)=v<<8
}

template <int L, int R>
__device__ __forceinline__ void gather_apply(const float2* __restrict__ st,
                                             const float4* __restrict__ Ug,
                                             int t, float* re, float* im) {
    const int base = abase<R>(t);
    #pragma unroll
    for (int v = 0; v < 16; ++v) {
        const float2 a = st[base ^ aoff<R>(v)];
        re[v] = a.x; im[v] = a.y;
    }
    #pragma unroll
    for (int lb = 0; lb < 4; ++lb) {
        const float4 g = Ug[L * NWIRES + (11 - (4 * R + lb))];
        const int str = 1 << lb;
        #pragma unroll
        for (int p = 0; p < 8; ++p) {
            const int i0 = ((p & ~(str - 1)) << 1) | (p & (str - 1));
            const int i1 = i0 | str;
            bfly(g, re[i0], im[i0], re[i1], im[i1]);
        }
    }
}
template <int R>
__device__ __forceinline__ void scatter(float2* __restrict__ st, int t,
                                        const float* re, const float* im) {
    const int base = abase<R>(t);
    #pragma unroll
    for (int v = 0; v < 16; ++v)
        st[base ^ aoff<R>(v)] = make_float2(re[v], im[v]);
}

__global__ __launch_bounds__(NT, 3)
void qnn_kernel(const float* __restrict__ x, const float* __restrict__ w,
                float* __restrict__ out)
{
    extern __shared__ char smem[];
    float2* buf0 = (float2*)smem;                      // layout A
    float2* buf1 = (float2*)(smem + OFF_BUF1);         // layout A (ping-pong)
    float4* Ug   = (float4*)(smem + OFF_UG);
    float2* sc   = (float2*)(smem + OFF_SC);
    float*  red  = (float*)(smem + OFF_RED);

    const int b = blockIdx.x;
    const int t = threadIdx.x;

    // ---- parallel sincos: one per thread ----
    if (t < 144) {
        float s, c;
        sincosf(0.5f * w[t], &s, &c);
        sc[t] = make_float2(c, s);
    } else if (t < 146) {
        float s, c;
        sincosf(0.5f * x[b * 2 + (t - 144)], &s, &c);
        sc[t] = make_float2(c, s);
    }
    __syncthreads();

    // ---- assemble fused SU(2) gates U = RZ RY RX @ Enc (48 threads) ----
    if (t < NLAYERS * NWIRES) {
        const int wi = t % NWIRES;
        const float2 A  = sc[t * 3 + 0];
        const float2 Bc = sc[t * 3 + 1];
        const float2 G  = sc[t * 3 + 2];
        float2 m00 = make_float2( Bc.x * A.x,  Bc.y * A.y);
        float2 m01 = make_float2(-Bc.y * A.x, -Bc.x * A.y);
        const float2 e0 = make_float2(G.x, -G.y);
        m00 = cmul(e0, m00); m01 = cmul(e0, m01);
        const float2 E = sc[144 + (wi & 1)];
        float2 u00, u01;
        if (wi & 1) { // RY encoding
            u00 = make_float2(fmaf(m00.x, E.x,  m01.x * E.y),
                              fmaf(m00.y, E.x,  m01.y * E.y));
            u01 = make_float2(fmaf(m00.x, -E.y, m01.x * E.x),
                              fmaf(m00.y, -E.y, m01.y * E.x));
        } else {      // RX encoding
            u00 = make_float2(fmaf(m00.x, E.x,  m01.y * E.y),
                              fmaf(m00.y, E.x, -(m01.x * E.y)));
            u01 = make_float2(fmaf(m01.x, E.x,  m00.y * E.y),
                              fmaf(m01.y, E.x, -(m00.x * E.y)));
        }
        Ug[t] = make_float4(u00.x, u00.y, u01.x, u01.y);
    }
    __syncthreads();

    const int hb = pj(hperm(t));   // runtime part of the h-scatter address

    // ---- layer 0 on |0..0>: product state via tensor tree, h-stored to buf0 ----
    {
        float2 pt = make_float2(1.f, 0.f);
        #pragma unroll
        for (int bit = 0; bit < 8; ++bit) {
            const int row = (t >> bit) & 1;
            const float4 g = Ug[11 - bit];
            const float cr = row ? -g.z : g.x;
            const float ci = row ?  g.w : g.y;
            pt = cmul(make_float2(cr, ci), pt);
        }
        float2 e3[2], e2[2], e1[2], e0c[2];
        {
            const float4 g3 = Ug[3], g2 = Ug[2], g1 = Ug[1], g0 = Ug[0];
            e3[0] = make_float2(g3.x, g3.y);  e3[1] = make_float2(-g3.z, g3.w);
            e2[0] = make_float2(g2.x, g2.y);  e2[1] = make_float2(-g2.z, g2.w);
            e1[0] = make_float2(g1.x, g1.y);  e1[1] = make_float2(-g1.z, g1.w);
            e0c[0] = make_float2(g0.x, g0.y); e0c[1] = make_float2(-g0.z, g0.w);
        }
        float2 PA[4], PB[4];
        #pragma unroll
        for (int a = 0; a < 4; ++a)
            PA[a] = cmul(cmul(e3[a & 1], e2[(a >> 1) & 1]), pt);
        #pragma unroll
        for (int bb = 0; bb < 4; ++bb)
            PB[bb] = cmul(e1[bb & 1], e0c[(bb >> 1) & 1]);
        #pragma unroll
        for (int v = 0; v < 16; ++v)
            buf0[hb ^ pj(hperm(v << 8))] = cmul(PA[v & 3], PB[v >> 2]);
    }
    __syncthreads();

    float re[16], im[16];

    // ---- layers 1,2: all rounds in buffer I; h-scatter into buffer O ----
    // (ping-pong removes the WAR hazard -> no pre-h barrier; h-stores overlap
    //  lagging warps' round-2 gathers of I)
    #define DO_LAYER(L, I, O)                                                  \
        gather_apply0<L>(I, Ug, t, re, im);                                    \
        scatter0(I, t, re, im);                                                \
        __syncwarp();                          /* round0<->round1: warp-local */\
        gather_apply<L, 1>(I, Ug, t, re, im);                                  \
        scatter<1>(I, t, re, im);                                              \
        __syncthreads();                                                       \
        gather_apply<L, 2>(I, Ug, t, re, im);                                  \
        _Pragma("unroll")                                                      \
        for (int v = 0; v < 16; ++v)                                           \
            O[hb ^ pj(hperm(v << 8))] = make_float2(re[v], im[v]);             \
        __syncthreads();

    DO_LAYER(1, buf0, buf1)
    DO_LAYER(2, buf1, buf0)

    // ---- layer 3: rounds 0,1 in buf0; round 2 fused with measurement ----
    gather_apply0<3>(buf0, Ug, t, re, im);
    scatter0(buf0, t, re, im);
    __syncwarp();
    gather_apply<3, 1>(buf0, Ug, t, re, im);
    scatter<1>(buf0, t, re, im);
    __syncthreads();
    gather_apply<3, 2>(buf0, Ug, t, re, im);

    // ---- measurement straight from registers ----
    float acc0 = 0.f, acc1 = 0.f, acc2 = 0.f, dpar = 0.f;
    #pragma unroll
    for (int v = 0; v < 16; ++v) {
        const float p = fmaf(re[v], re[v], im[v] * im[v]);
        const int v3 = (v >> 3) & 1, v2 = (v >> 2) & 1, v1 = (v >> 1) & 1, v0 = v & 1;
        acc0 += v3 ? -p : p;
        acc1 += (v3 ^ v2) ? -p : p;
        acc2 += (v3 ^ v2 ^ v1) ? -p : p;
        dpar += (v3 ^ v2 ^ v1 ^ v0) ? -p : p;
    }
    const int t4 = (t >> 4) & 1;
    float d4 = t4 ? -dpar : dpar;

    const unsigned FULL = 0xffffffffu;
    float vals[5] = {acc0, acc1, acc2, dpar, d4};
    #pragma unroll
    for (int i = 0; i < 5; ++i) {
        float v = vals[i];
        #pragma unroll
        for (int o = 16; o > 0; o >>= 1) v += __shfl_xor_sync(FULL, v, o);
        vals[i] = v;
    }
    if ((t & 31) == 0) {
        const int wp = t >> 5;
        const int t7 = (t >> 7) & 1, t6 = (t >> 6) & 1, t5 = (t >> 5) & 1;
        const float D = vals[3], D4 = vals[4];
        red[wp * 8 + 0] = vals[0];
        red[wp * 8 + 1] = vals[1];
        red[wp * 8 + 2] = vals[2];
        red[wp * 8 + 3] = D;
        red[wp * 8 + 4] = t7 ? -D : D;
        red[wp * 8 + 5] = (t7 ^ t6) ? -D : D;
        red[wp * 8 + 6] = (t7 ^ t6 ^ t5) ? -D : D;
        red[wp * 8 + 7] = (t7 ^ t6 ^ t5) ? -D4 : D4;
    }
    __syncthreads();
    if (t < 8) {
        float s = 0.f;
        #pragma unroll
        for (int wp2 = 0; wp2 < 8; ++wp2) s += red[wp2 * 8 + t];
        out[b * 8 + t] = s * 3.14159265358979f;
    }
}

extern "C" void kernel_launch(void* const* d_in, const int* in_sizes, int n_in,
                              void* d_out, int out_size) {
    const float* x = (const float*)d_in[0];   // [B, 2]
    const float* w = (const float*)d_in[1];   // [4, 12, 3]
    float* out = (float*)d_out;               // [B, 8]
    const int B = in_sizes[0] / 2;
    cudaFuncSetAttribute(qnn_kernel, cudaFuncAttributeMaxDynamicSharedMemorySize, SMEM_TOTAL);
    qnn_kernel<<<B, NT, SMEM_TOTAL>>>(x, w, out);
}